// round 11
// baseline (speedup 1.0000x reference)
#include <cuda_runtime.h>
#include <cuda_bf16.h>
#include <cstdint>

// Problem constants
#define B_  64
#define H_  128
#define W_  128
#define C_  3
#define KH_ 5
#define KW_ 5
#define N_  10
#define PAD_ 2
#define HW_ (H_ * W_)

#define RPB_   2     // output rows per block
#define FR_    6     // fill rows per block: h0-2 .. h0+3
#define SROWF_ 400   // smem floats per row: interior at [8..391], halos zeroed

__device__ __forceinline__ unsigned long long pk2(float lo, float hi) {
    unsigned long long r;
    asm("mov.b64 %0, {%1, %2};" : "=l"(r) : "f"(lo), "f"(hi));
    return r;
}
__device__ __forceinline__ void unpk2(unsigned long long p, float& lo, float& hi) {
    asm("mov.b64 {%0, %1}, %2;" : "=f"(lo), "=f"(hi) : "l"(p));
}
__device__ __forceinline__ unsigned long long ffma2(unsigned long long a,
                                                    unsigned long long b,
                                                    unsigned long long c) {
    unsigned long long d;
    asm("fma.rn.f32x2 %0, %1, %2, %3;" : "=l"(d) : "l"(a), "l"(b), "l"(c));
    return d;
}
__device__ __forceinline__ uint32_t smem_u32(const void* p) {
    uint32_t a;
    asm("{ .reg .u64 t; cvta.to.shared.u64 t, %1; cvt.u32.u64 %0, t; }" : "=r"(a) : "l"(p));
    return a;
}
__device__ __forceinline__ void cp_async16(uint32_t dst, const void* src) {
    asm volatile("cp.async.cg.shared.global [%0], [%1], 16;" :: "r"(dst), "l"(src) : "memory");
}

// Channel-split layout: each thread owns ONE (pixel, channel) and all 10 n
// outputs as 5 n-packed f32x2 accs (10 regs). Block = 128 w x 3 c x 2 rows
// = 768 threads; ~40 regs -> 2 CTAs/SM = 48 warps (75% occ) for latency
// coverage. w is the fastest thread index -> coalesced STG, stride-3
// conflict-free img LDS; weight loads are warp-uniform broadcasts.
extern "C" __global__ void __launch_bounds__(768, 2)
cdna_apply_kernel(const float* __restrict__ images,
                  const float* __restrict__ kernels,
                  float* __restrict__ out) {
    const int b  = blockIdx.y;          // batch
    const int h0 = blockIdx.x * RPB_;   // first of 2 output rows this block owns

    __shared__ __align__(16) float s_img[FR_][SROWF_];  // 9,600 B
    __shared__ __align__(16) float s_ker[25][12];       // n-pairs, tap row padded

    const int tid = threadIdx.x;
    const float* img = images  + (size_t)b * (H_ * W_ * C_);
    const float* ker = kernels + b * (KH_ * KW_ * N_);

    // --- zero the whole image tile (covers halos + out-of-range rows) ---
    {
        float4* p = reinterpret_cast<float4*>(&s_img[0][0]);
        for (int i = tid; i < (FR_ * SROWF_) / 4; i += 768)   // 600 float4
            p[i] = make_float4(0.f, 0.f, 0.f, 0.f);
    }
    // weights (n-contiguous pairs)
    if (tid < 250) {
        const int tap = tid / 10;
        const int n   = tid - tap * 10;
        s_ker[tap][n] = ker[tid];
    }
    __syncthreads();

    // --- interior fill via cp.async: 6 rows x 96 float4 = 576 copies ---
    for (int i = tid; i < FR_ * 96; i += 768) {
        const int r    = i / 96;
        const int col4 = i - r * 96;
        const int gr   = h0 - 2 + r;
        if ((unsigned)gr < (unsigned)H_) {
            const uint32_t dst = smem_u32(&s_img[r][8 + col4 * 4]);
            cp_async16(dst, img + gr * (W_ * C_) + col4 * 4);
        }
    }
    asm volatile("cp.async.commit_group;" ::: "memory");
    asm volatile("cp.async.wait_group 0;" ::: "memory");
    __syncthreads();

    const int w  = tid & 127;          // output column (fastest -> coalesced)
    const int c  = (tid >> 7) % 3;     // channel
    const int hr = tid / 384;          // row within block (0/1)

    // acc[n_pair] packed fp32x2 over n (lo = n=2j, hi = n=2j+1)
    unsigned long long acc[5];
#pragma unroll
    for (int j = 0; j < 5; ++j) acc[j] = 0ull;

    // tap (dh,dw) for this thread's (w,c): base[dh*SROWF_ + 3*dw]
    const float* base = &s_img[hr][3 * w + 2 + c];

#pragma unroll
    for (int dh = 0; dh < 5; ++dh) {
        const float* row = base + dh * SROWF_;
#pragma unroll
        for (int dw = 0; dw < 5; ++dw) {
            const float v = row[3 * dw];
            const unsigned long long iv = pk2(v, v);
            const float* kp = &s_ker[dh * 5 + dw][0];
            const ulonglong2 wA = *reinterpret_cast<const ulonglong2*>(kp);      // pairs 0,1
            const ulonglong2 wB = *reinterpret_cast<const ulonglong2*>(kp + 4);  // pairs 2,3
            const unsigned long long w4 =
                *reinterpret_cast<const unsigned long long*>(kp + 8);            // pair 4

            acc[0] = ffma2(iv, wA.x, acc[0]);
            acc[1] = ffma2(iv, wA.y, acc[1]);
            acc[2] = ffma2(iv, wB.x, acc[2]);
            acc[3] = ffma2(iv, wB.y, acc[3]);
            acc[4] = ffma2(iv, w4,   acc[4]);
        }
    }

    // --- store: out[n][b][c][h][w], 10 coalesced STG.32 per thread ---
    const int hpix = h0 + hr;
    float* o = out + ((size_t)b * C_ + c) * HW_ + hpix * W_ + w;  // n=0
#pragma unroll
    for (int j = 0; j < 5; ++j) {
        float lo, hi;
        unpk2(acc[j], lo, hi);
        o[(size_t)(2 * j)     * (B_ * C_ * HW_)] = lo;
        o[(size_t)(2 * j + 1) * (B_ * C_ * HW_)] = hi;
    }
}

extern "C" void kernel_launch(void* const* d_in, const int* in_sizes, int n_in,
                              void* d_out, int out_size) {
    const float* images  = (const float*)d_in[0];  // [64,128,128,3]
    const float* kernels = (const float*)d_in[1];  // [64,5,5,10]
    float* out = (float*)d_out;                    // [10,64,3,128,128]
    (void)in_sizes; (void)n_in; (void)out_size;

    dim3 grid(H_ / RPB_, B_);   // 64 x 64 blocks
    dim3 block(768);
    cdna_apply_kernel<<<grid, block>>>(images, kernels, out);
}

// round 13
// speedup vs baseline: 1.5696x; 1.5696x over previous
#include <cuda_runtime.h>
#include <cuda_bf16.h>
#include <cstdint>

// Problem constants
#define B_  64
#define H_  128
#define W_  128
#define C_  3
#define KH_ 5
#define KW_ 5
#define N_  10
#define PAD_ 2
#define HW_ (H_ * W_)

#define RPB_   4     // output rows per block
#define FR_    8     // fill rows: h0-2 .. h0+5
#define SCRW_  404   // scratch row floats: col x at 8+3x+c, x in [-2,130]
#define NP_    66    // phase entries per (c,row): j in [0,65]

__device__ __forceinline__ unsigned long long pk2(float lo, float hi) {
    unsigned long long r;
    asm("mov.b64 %0, {%1, %2};" : "=l"(r) : "f"(lo), "f"(hi));
    return r;
}
__device__ __forceinline__ unsigned long long ffma2(unsigned long long a,
                                                    unsigned long long b,
                                                    unsigned long long c) {
    unsigned long long d;
    asm("fma.rn.f32x2 %0, %1, %2, %3;" : "=l"(d) : "l"(a), "l"(b), "l"(c));
    return d;
}
__device__ __forceinline__ uint32_t smem_u32(const void* p) {
    uint32_t a;
    asm("{ .reg .u64 t; cvta.to.shared.u64 t, %1; cvt.u32.u64 %0, t; }" : "=r"(a) : "l"(p));
    return a;
}
__device__ __forceinline__ void cp_async16(uint32_t dst, const void* src) {
    asm volatile("cp.async.cg.shared.global [%0], [%1], 16;" :: "r"(dst), "l"(src) : "memory");
}

// Pixel-pair packing: f32x2 lanes = pixels (w0, w0+1). Thread owns 60 outputs
// (2px x 10n x 3c) as 30 u64 accs. Dual-phase smem image (p0[j]=(v2j-2,v2j-1),
// p1[j]=(v2j-1,v2j)) makes every dw-shift ONE aligned conflict-free LDS.64.
// Tap mapping: output pair (2p,2p+1), tap dw needs cols (2p+dw-2, 2p+dw-1)
//   dw=0 -> p0[p], dw=1 -> p1[p], dw=2 -> p0[p+1], dw=3 -> p1[p+1], dw=4 -> p0[p+2]
//   i.e. phase = dw&1, j = p + (dw>>1).            (R12 bug: used (dw+1)/2)
extern "C" __global__ void __launch_bounds__(256, 3)
cdna_apply_kernel(const float* __restrict__ images,
                  const float* __restrict__ kernels,
                  float* __restrict__ out) {
    const int b  = blockIdx.y;          // batch
    const int h0 = blockIdx.x * RPB_;   // first of 4 output rows

    __shared__ __align__(16) float s_row[FR_][SCRW_];                 // 12,928 B
    __shared__ __align__(16) unsigned long long s_p0[C_][FR_][NP_];   // 12,672 B
    __shared__ __align__(16) unsigned long long s_p1[C_][FR_][NP_];   // 12,672 B
    __shared__ __align__(16) unsigned long long s_kd[25][10];         // dup wts, 2,000 B

    const int tid = threadIdx.x;
    const float* img = images  + (size_t)b * (H_ * W_ * C_);
    const float* ker = kernels + b * (KH_ * KW_ * N_);

    // --- zero scratch (halos + out-of-range rows) ---
    {
        float4* p = reinterpret_cast<float4*>(&s_row[0][0]);
        for (int i = tid; i < (FR_ * SCRW_) / 4; i += 256)
            p[i] = make_float4(0.f, 0.f, 0.f, 0.f);
    }
    // duplicated weights
    if (tid < 250) {
        const int tap = tid / 10;
        const int n   = tid - tap * 10;
        const float v = ker[tid];
        s_kd[tap][n] = pk2(v, v);
    }
    __syncthreads();

    // --- interior fill via cp.async: 8 rows x 96 float4 ---
    for (int i = tid; i < FR_ * 96; i += 256) {
        const int r    = i / 96;
        const int col4 = i - r * 96;
        const int gr   = h0 - 2 + r;
        if ((unsigned)gr < (unsigned)H_) {
            const uint32_t dst = smem_u32(&s_row[r][8 + col4 * 4]);
            cp_async16(dst, img + gr * (W_ * C_) + col4 * 4);
        }
    }
    asm volatile("cp.async.commit_group;" ::: "memory");
    asm volatile("cp.async.wait_group 0;" ::: "memory");
    __syncthreads();

    // --- rearrange into dual-phase pair arrays ---
    // col x lives at s_row[r][8+3x+c]. p0[j]=(v(2j-2),v(2j-1)); p1[j]=(v(2j-1),v(2j)).
    for (int idx = tid; idx < C_ * FR_ * NP_; idx += 256) {
        const int c   = idx / (FR_ * NP_);
        const int rem = idx - c * (FR_ * NP_);
        const int r   = rem / NP_;
        const int j   = rem - r * NP_;
        const float* sr = &s_row[r][8 + c];
        const float va = sr[3 * (2 * j - 2)];
        const float vb = sr[3 * (2 * j - 1)];
        const float vc = sr[3 * (2 * j)];
        s_p0[c][r][j] = pk2(va, vb);
        s_p1[c][r][j] = pk2(vb, vc);
    }
    __syncthreads();

    const int p  = tid & 63;    // pair index; pixels w0=2p, w0+1
    const int hr = tid >> 6;    // row within block (0..3)

    // acc[n][c]: f32x2 lanes = (pixel 2p, pixel 2p+1)
    unsigned long long acc[N_][C_];
#pragma unroll
    for (int n = 0; n < N_; ++n)
#pragma unroll
        for (int c = 0; c < C_; ++c) acc[n][c] = 0ull;

#pragma unroll
    for (int dh = 0; dh < 5; ++dh) {
#pragma unroll
        for (int dw = 0; dw < 5; ++dw) {
            // iv per channel: ONE aligned LDS.64 from the right phase array
            const int j = p + (dw >> 1);           // p, p, p+1, p+1, p+2
            const unsigned long long* ph =
                (dw & 1) ? &s_p1[0][0][0] : &s_p0[0][0][0];
            const int ro = (hr + dh) * NP_ + j;
            const unsigned long long iv0 = ph[0 * (FR_ * NP_) + ro];
            const unsigned long long iv1 = ph[1 * (FR_ * NP_) + ro];
            const unsigned long long iv2 = ph[2 * (FR_ * NP_) + ro];

            // duplicated weights: 5 broadcast LDS.128 (2 n each)
            const unsigned long long* kt = &s_kd[dh * 5 + dw][0];
            const ulonglong2 k01 = *reinterpret_cast<const ulonglong2*>(kt);
            const ulonglong2 k23 = *reinterpret_cast<const ulonglong2*>(kt + 2);
            const ulonglong2 k45 = *reinterpret_cast<const ulonglong2*>(kt + 4);
            const ulonglong2 k67 = *reinterpret_cast<const ulonglong2*>(kt + 6);
            const ulonglong2 k89 = *reinterpret_cast<const ulonglong2*>(kt + 8);

            acc[0][0] = ffma2(iv0, k01.x, acc[0][0]);
            acc[0][1] = ffma2(iv1, k01.x, acc[0][1]);
            acc[0][2] = ffma2(iv2, k01.x, acc[0][2]);
            acc[1][0] = ffma2(iv0, k01.y, acc[1][0]);
            acc[1][1] = ffma2(iv1, k01.y, acc[1][1]);
            acc[1][2] = ffma2(iv2, k01.y, acc[1][2]);
            acc[2][0] = ffma2(iv0, k23.x, acc[2][0]);
            acc[2][1] = ffma2(iv1, k23.x, acc[2][1]);
            acc[2][2] = ffma2(iv2, k23.x, acc[2][2]);
            acc[3][0] = ffma2(iv0, k23.y, acc[3][0]);
            acc[3][1] = ffma2(iv1, k23.y, acc[3][1]);
            acc[3][2] = ffma2(iv2, k23.y, acc[3][2]);
            acc[4][0] = ffma2(iv0, k45.x, acc[4][0]);
            acc[4][1] = ffma2(iv1, k45.x, acc[4][1]);
            acc[4][2] = ffma2(iv2, k45.x, acc[4][2]);
            acc[5][0] = ffma2(iv0, k45.y, acc[5][0]);
            acc[5][1] = ffma2(iv1, k45.y, acc[5][1]);
            acc[5][2] = ffma2(iv2, k45.y, acc[5][2]);
            acc[6][0] = ffma2(iv0, k67.x, acc[6][0]);
            acc[6][1] = ffma2(iv1, k67.x, acc[6][1]);
            acc[6][2] = ffma2(iv2, k67.x, acc[6][2]);
            acc[7][0] = ffma2(iv0, k67.y, acc[7][0]);
            acc[7][1] = ffma2(iv1, k67.y, acc[7][1]);
            acc[7][2] = ffma2(iv2, k67.y, acc[7][2]);
            acc[8][0] = ffma2(iv0, k89.x, acc[8][0]);
            acc[8][1] = ffma2(iv1, k89.x, acc[8][1]);
            acc[8][2] = ffma2(iv2, k89.x, acc[8][2]);
            acc[9][0] = ffma2(iv0, k89.y, acc[9][0]);
            acc[9][1] = ffma2(iv1, k89.y, acc[9][1]);
            acc[9][2] = ffma2(iv2, k89.y, acc[9][2]);
        }
    }

    // --- store: out[n][b][c][h][w0..w0+1] -> STG.64, coalesced ---
    const int hpix = h0 + hr;
    const int w0   = 2 * p;
    char* o0 = reinterpret_cast<char*>(out)
             + (((size_t)b * C_) * HW_ + hpix * W_ + w0) * sizeof(float);
#pragma unroll
    for (int n = 0; n < N_; ++n) {
        char* on = o0 + (size_t)n * (B_ * C_ * HW_) * sizeof(float);
#pragma unroll
        for (int c = 0; c < C_; ++c)
            *reinterpret_cast<unsigned long long*>(on + (size_t)c * HW_ * sizeof(float))
                = acc[n][c];
    }
}

extern "C" void kernel_launch(void* const* d_in, const int* in_sizes, int n_in,
                              void* d_out, int out_size) {
    const float* images  = (const float*)d_in[0];  // [64,128,128,3]
    const float* kernels = (const float*)d_in[1];  // [64,5,5,10]
    float* out = (float*)d_out;                    // [10,64,3,128,128]
    (void)in_sizes; (void)n_in; (void)out_size;

    dim3 grid(H_ / RPB_, B_);   // 32 x 64 blocks
    dim3 block(256);
    cdna_apply_kernel<<<grid, block>>>(images, kernels, out);
}